// round 17
// baseline (speedup 1.0000x reference)
#include <cuda_runtime.h>
#include <cuda_fp16.h>
#include <cstdint>

// GRU: B=128, T=4096, I=6, H=32, O=2. One CTA per sequence, 4 warps:
//   warp 0: recurrence, mixed tensor GEMV, 10 MMAs, chain-optimized:
//     r gate: 4x f16 mma.m16n8k16 (2 m-tiles x 2 INDEPENDENT k-halves),
//       gx.x folded into the k0 C-operand (off-chain SELs) -> after MMA the
//       critical path is just SEL+FADD+tanh. No I2F (R16's int8 r had ~20cyc
//       I2F on the chain; R14/R16 comparison proved MMA *count* is cheap).
//     n gate: 4x independent f16 MMAs, bias in C (precision-critical path).
//     z gate: 2x int8 mma.m16n8k32 (I2F/dequant on the slack path).
//   h kept in THREE forms: f32 (FC, exact), f16 (r,n dots), s8 (z dots).
//   gx prefetched one step ahead (C-seeds never wait on LDS).
//   warp 1: FC output, one chunk behind (exact f32 h ring)
//   warps 2,3: gx producers, one chunk ahead (f32)
// Unit ownership follows the MMA D-fragment: u = gid + 8*(tig&1) + 16*(tig>>1).

#define Bq 128
#define Tq 4096
#define Iq 6
#define Hq 32
#define Oq 2
#define CH 32
#define NCH (Tq / CH)
#define HPAD 36   // f32 h ring rows: 144B

__device__ __forceinline__ float tanhm(float x) { float y; asm("tanh.approx.f32 %0, %1;" : "=f"(y) : "f"(x)); return y; }

__device__ __forceinline__ uint32_t saddr(const void* p) {
    uint32_t a;
    asm("{ .reg .u64 t; cvta.to.shared.u64 t, %1; cvt.u32.u64 %0, t; }" : "=r"(a) : "l"(p));
    return a;
}
__device__ __forceinline__ uint32_t ldv32(uint32_t a) {
    uint32_t v; asm volatile("ld.volatile.shared.b32 %0, [%1];" : "=r"(v) : "r"(a)); return v;
}
__device__ __forceinline__ void stv16(uint32_t a, unsigned short v) {
    asm volatile("st.volatile.shared.u16 [%0], %1;" :: "r"(a), "h"(v));
}
__device__ __forceinline__ void stv8(uint32_t a, uint32_t v) {
    asm volatile("st.volatile.shared.u8 [%0], %1;" :: "r"(a), "r"(v));
}
__device__ __forceinline__ void sts32p(uint32_t a, float v) {
    asm volatile("st.shared.f32 [%0], %1;" :: "r"(a), "f"(v));
}
__device__ __forceinline__ uint32_t packh2(float lo, float hi) {
    __half2 h = __floats2half2_rn(lo, hi);
    return *(uint32_t*)&h;
}

// f16: D (f32, fresh) = A*B + Cq
#define MMA_LD(D, A, B0, B1, C0, C1, C2, C3)                                   \
    asm volatile(                                                              \
        "mma.sync.aligned.m16n8k16.row.col.f32.f16.f16.f32 "                   \
        "{%0,%1,%2,%3}, {%4,%5,%6,%7}, {%8,%9}, {%10,%11,%12,%13};"            \
        : "=f"((D)[0]), "=f"((D)[1]), "=f"((D)[2]), "=f"((D)[3])               \
        : "r"((A)[0]), "r"((A)[1]), "r"((A)[2]), "r"((A)[3]),                  \
          "r"(B0), "r"(B1),                                                    \
          "f"(C0), "f"(C1), "f"(C2), "f"(C3))

// int8: D (s32, fresh) = A*B
#define MMAI(D, A, B0, B1)                                                     \
    asm volatile(                                                              \
        "mma.sync.aligned.m16n8k32.row.col.s32.s8.s8.s32 "                     \
        "{%0,%1,%2,%3}, {%4,%5,%6,%7}, {%8,%9}, {%10,%11,%12,%13};"            \
        : "=r"((D)[0]), "=r"((D)[1]), "=r"((D)[2]), "=r"((D)[3])               \
        : "r"((A)[0]), "r"((A)[1]), "r"((A)[2]), "r"((A)[3]),                  \
          "r"(B0), "r"(B1),                                                    \
          "r"(0), "r"(0), "r"(0), "r"(0))

__global__ void __launch_bounds__(128, 1) gru_seq_kernel(
    const float* __restrict__ x,        // [B, T, I]
    const int*   __restrict__ lengths,  // [B]
    const float* __restrict__ w_ih,     // [3H, I]
    const float* __restrict__ w_hh,     // [3H, H]  (96 x 32 row-major)
    const float* __restrict__ b_ih,     // [3H]
    const float* __restrict__ b_hh,     // [3H]
    const float* __restrict__ fc_w,     // [O, H]
    const float* __restrict__ fc_b,     // [O]
    float* __restrict__ out)            // [B, T, O]
{
    __shared__ __align__(16) float4  s_gx[2][CH][Hq];   // {pr, pz, pn, 0} by hidden unit
    __shared__ __align__(16) float   s_h[2][CH][HPAD];  // f32 h ring (for FC)
    __shared__ __align__(16) __half  s_h16[2][CH][Hq];  // f16 h ring (r,n dots)
    __shared__ __align__(4)  uint8_t s_h8[2][CH][Hq];   // s8 h ring (z dots)
    __shared__ float s_scale[Hq];                       // per-row |w|max (z rows)

    const int lane = threadIdx.x & 31;
    const int warp = threadIdx.x >> 5;
    const int b = blockIdx.x;
    const int L = lengths[b];

    const uint32_t hbase   = saddr(&s_h[0][0][0]);
    const uint32_t h16base = saddr(&s_h16[0][0][0]);
    const uint32_t h8base  = saddr(&s_h8[0][0][0]);

    if (warp == 0) {
        // ================= recurrence (mixed f16/int8 tensor GEMV) =========
        const int gid = lane >> 2;          // groupID (0..7)
        const int tig = lane & 3;           // thread-in-group
        const int u = gid + ((tig & 1) << 3) + ((tig & 2) << 3);  // owned hidden unit
        const bool p0 = (tig == 0), p1 = (tig == 1), p2 = (tig == 2), p3 = (tig == 3);
        const bool pt2 = (tig & 2) != 0;

        // --- per-row weight scales for z rows (setup) ---
        {
            int r = lane;
            float m = 0.0f;
            const float* wr = w_hh + (Hq + r) * Hq;
#pragma unroll
            for (int k = 0; k < Hq; k++) m = fmaxf(m, fabsf(wr[k]));
            s_scale[r] = (m > 0.0f) ? m : 1.0f;
        }
        __syncwarp();

        // --- f16 A fragments for r: 2 m-tiles x 2 k-halves, 0.5-scaled ---
        uint32_t afr[2][2][4];
#pragma unroll
        for (int mt = 0; mt < 2; mt++)
#pragma unroll
            for (int kt = 0; kt < 2; kt++) {
                const int r0 = mt * 16 + gid;
                const int r1 = r0 + 8;
                const int c0 = kt * 16 + 2 * tig;
                afr[mt][kt][0] = packh2(0.5f * w_hh[r0 * Hq + c0],     0.5f * w_hh[r0 * Hq + c0 + 1]);
                afr[mt][kt][1] = packh2(0.5f * w_hh[r1 * Hq + c0],     0.5f * w_hh[r1 * Hq + c0 + 1]);
                afr[mt][kt][2] = packh2(0.5f * w_hh[r0 * Hq + c0 + 8], 0.5f * w_hh[r0 * Hq + c0 + 9]);
                afr[mt][kt][3] = packh2(0.5f * w_hh[r1 * Hq + c0 + 8], 0.5f * w_hh[r1 * Hq + c0 + 9]);
            }
        // --- f16 A fragments for n: 2 m-tiles x 2 k-halves, 0.5-scaled ---
        uint32_t afn[2][2][4];
#pragma unroll
        for (int mt = 0; mt < 2; mt++)
#pragma unroll
            for (int kt = 0; kt < 2; kt++) {
                const int r0 = 2 * Hq + mt * 16 + gid;
                const int r1 = r0 + 8;
                const int c0 = kt * 16 + 2 * tig;
                afn[mt][kt][0] = packh2(0.5f * w_hh[r0 * Hq + c0],     0.5f * w_hh[r0 * Hq + c0 + 1]);
                afn[mt][kt][1] = packh2(0.5f * w_hh[r1 * Hq + c0],     0.5f * w_hh[r1 * Hq + c0 + 1]);
                afn[mt][kt][2] = packh2(0.5f * w_hh[r0 * Hq + c0 + 8], 0.5f * w_hh[r0 * Hq + c0 + 9]);
                afn[mt][kt][3] = packh2(0.5f * w_hh[r1 * Hq + c0 + 8], 0.5f * w_hh[r1 * Hq + c0 + 9]);
            }
        // --- int8 A fragments for z: 2 m-tiles (rows Hq..2Hq), per-row scales ---
        uint32_t afz[2][4];
#pragma unroll
        for (int t = 0; t < 2; t++) {
            const int zr0 = t * 16 + gid;       // z-row index (0..31)
            const int zr1 = zr0 + 8;
            const int r0 = Hq + zr0;
            const int r1 = Hq + zr1;
            const float is0 = 127.0f / s_scale[zr0];
            const float is1 = 127.0f / s_scale[zr1];
            const int klo = 4 * tig, khi = 16 + 4 * tig;
            uint32_t v0 = 0, v1 = 0, v2 = 0, v3 = 0;
#pragma unroll
            for (int j = 0; j < 4; j++) {
                int q0 = __float2int_rn(w_hh[r0 * Hq + klo + j] * is0);
                int q1 = __float2int_rn(w_hh[r1 * Hq + klo + j] * is1);
                int q2 = __float2int_rn(w_hh[r0 * Hq + khi + j] * is0);
                int q3 = __float2int_rn(w_hh[r1 * Hq + khi + j] * is1);
                v0 |= (uint32_t)(q0 & 0xFF) << (8 * j);
                v1 |= (uint32_t)(q1 & 0xFF) << (8 * j);
                v2 |= (uint32_t)(q2 & 0xFF) << (8 * j);
                v3 |= (uint32_t)(q3 & 0xFF) << (8 * j);
            }
            afz[t][0] = v0; afz[t][1] = v1; afz[t][2] = v2; afz[t][3] = v3;
        }
        // n-tile bias C-quads (0.5*bhn by row) on the k0 MMA
        const float bn0a = 0.5f * b_hh[2 * Hq + gid];
        const float bn0b = 0.5f * b_hh[2 * Hq + gid + 8];
        const float bn1a = 0.5f * b_hh[2 * Hq + 16 + gid];
        const float bn1b = 0.5f * b_hh[2 * Hq + 24 + gid];
        const float fzr = 0.0f;
        // z dequant: 0.5 gate-fold + h scale 1/127 + weight scale/127
        const float fzc = (0.5f / (127.0f * 127.0f)) * s_scale[u];

        // h_{-1} = 0 rows (f16 + s8)
        stv16(h16base + ((1 * CH + (CH - 1)) * Hq + u) * 2, (unsigned short)0);
        stv8(h8base + ((1 * CH + (CH - 1)) * Hq + u), 0u);
        float hk = 0.f;
        uint32_t hprev16 = h16base + ((1 * CH + (CH - 1)) * Hq) * 2;
        uint32_t hprev8  = h8base + ((1 * CH + (CH - 1)) * Hq);
        const uint32_t tig4 = tig * 4;

#define GRU_STEP(CBUF, S, NST, H16ROW, H8ROW, HROWF)                           \
        {                                                                      \
            /* f16 B fragments (r,n) first — r is the critical gate */         \
            uint32_t b0 = ldv32(hprev16 + tig4);                               \
            uint32_t b1 = ldv32(hprev16 + 16 + tig4);                          \
            uint32_t b2 = ldv32(hprev16 + 32 + tig4);                          \
            uint32_t b3 = ldv32(hprev16 + 48 + tig4);                          \
            /* off-chain C seeds from PREFETCHED gx (no LDS wait) */           \
            float crA0 = p0 ? gx.x : 0.f, crA2 = p1 ? gx.x : 0.f;              \
            float crB0 = p2 ? gx.x : 0.f, crB2 = p3 ? gx.x : 0.f;              \
            float dR0a[4], dR0b[4], dR1a[4], dR1b[4];                          \
            MMA_LD(dR0a, afr[0][0], b0, b1, crA0, fzr, crA2, fzr);             \
            MMA_LD(dR0b, afr[0][1], b2, b3, fzr, fzr, fzr, fzr);               \
            MMA_LD(dR1a, afr[1][0], b0, b1, crB0, fzr, crB2, fzr);             \
            MMA_LD(dR1b, afr[1][1], b2, b3, fzr, fzr, fzr, fzr);               \
            float dN0a[4], dN0b[4], dN1a[4], dN1b[4];                          \
            MMA_LD(dN0a, afn[0][0], b0, b1, bn0a, fzr, bn0b, fzr);             \
            MMA_LD(dN0b, afn[0][1], b2, b3, fzr, fzr, fzr, fzr);               \
            MMA_LD(dN1a, afn[1][0], b0, b1, bn1a, fzr, bn1b, fzr);             \
            MMA_LD(dN1b, afn[1][1], b2, b3, fzr, fzr, fzr, fzr);               \
            /* int8 B fragments + z MMAs (slack path) */                       \
            uint32_t c0 = ldv32(hprev8 + tig4);                                \
            uint32_t c1 = ldv32(hprev8 + 16 + tig4);                           \
            int dZ0[4], dZ1[4];                                                \
            MMAI(dZ0, afz[0], c0, c1);                                         \
            MMAI(dZ1, afz[1], c0, c1);                                         \
            float pzv = gx.y, pnv = gx.z;                                      \
            /* prefetch next step's gx (off-chain) */                          \
            int sn_ = (S) + 1; if (sn_ >= (NST)) sn_ = 0;                      \
            float4 gxn = s_gx[CBUF][sn_][u];                                   \
            /* r: SEL halves, merge, tanh (gx.x already inside k0 C) */        \
            float rA = pt2 ? (p3 ? dR1a[2] : dR1a[0]) : (p1 ? dR0a[2] : dR0a[0]); \
            float rB = pt2 ? (p3 ? dR1b[2] : dR1b[0]) : (p1 ? dR0b[2] : dR0b[0]); \
            float tr = tanhm(rA + rB);                                         \
            float n0 = pt2 ? (p3 ? dN1a[2] : dN1a[0]) : (p1 ? dN0a[2] : dN0a[0]); \
            float n1 = pt2 ? (p3 ? dN1b[2] : dN1b[0]) : (p1 ? dN0b[2] : dN0b[0]); \
            float ns = n0 + n1;                      /* 0.5*(Wn.h + bhn) */    \
            float nsc = pnv + ns;                                              \
            float argn = fmaf(tr, ns, nsc);          /* xn + r*hn */           \
            float tn = tanhm(argn);                                            \
            float halfd = fmaf(0.5f, hk, -0.5f * tn);                          \
            float tph = tn + halfd;                  /* prepped in z shadow */ \
            int iZ = pt2 ? (p3 ? dZ1[2] : dZ1[0]) : (p1 ? dZ0[2] : dZ0[0]);    \
            float tz = tanhm(fmaf((float)iZ, fzc, pzv));                       \
            hk = fmaf(halfd, tz, tph);               /* h_new (f32) */         \
            stv16((H16ROW) + u * 2, __half_as_ushort(__float2half_rn(hk)));    \
            int hq = __float2int_rn(hk * 127.0f);                              \
            stv8((H8ROW) + u, (uint32_t)hq);                                   \
            sts32p((HROWF) + u * 4, hk);             /* exact copy for FC */   \
            hprev16 = (H16ROW);                                                \
            hprev8 = (H8ROW);                                                  \
            gx = gxn;                                                          \
        }

        for (int c = 0; c < NCH; c++) {
            __syncthreads();
            int nst = L - c * CH;
            nst = nst < 0 ? 0 : (nst > CH ? CH : nst);
            const int cb1 = c & 1;
            uint32_t h16row = h16base + (cb1 * CH * Hq) * 2;
            uint32_t h8row  = h8base + (cb1 * CH * Hq);
            uint32_t hrowf  = hbase + (cb1 * CH * HPAD) * 4;
            if (nst > 0) {
                float4 gx = s_gx[cb1][0][u];
                if (nst == CH) {
#pragma unroll 4
                    for (int s = 0; s < CH; s++) {
                        GRU_STEP(cb1, s, CH, h16row, h8row, hrowf)
                        h16row += Hq * 2;
                        h8row += Hq;
                        hrowf += HPAD * 4;
                    }
                } else {
#pragma unroll 1
                    for (int s = 0; s < nst; s++) {
                        GRU_STEP(cb1, s, nst, h16row, h8row, hrowf)
                        h16row += Hq * 2;
                        h8row += Hq;
                        hrowf += HPAD * 4;
                    }
                }
            }
        }
        __syncthreads();
#undef GRU_STEP
    } else if (warp == 1) {
        // ================= FC output, one chunk behind =================
        for (int c = 0; c < NCH; c++) {
            __syncthreads();
            if (c > 0) {
                const int cp = c - 1;
                const int t = cp * CH + lane;
                float o0 = __ldg(fc_b + 0);
                float o1 = __ldg(fc_b + 1);
                if (t < L) {
                    const float* hr = &s_h[cp & 1][lane][0];
#pragma unroll
                    for (int j = 0; j < Hq; j++) {
                        float hv = hr[j];
                        o0 = fmaf(__ldg(fc_w + j), hv, o0);
                        o1 = fmaf(__ldg(fc_w + Hq + j), hv, o1);
                    }
                }
                float2 v = make_float2(o0, o1);
                *reinterpret_cast<float2*>(out + ((size_t)b * Tq + t) * Oq) = v;
            }
        }
        __syncthreads();
        {   // epilogue: last chunk
            const int cp = NCH - 1;
            const int t = cp * CH + lane;
            float o0 = __ldg(fc_b + 0);
            float o1 = __ldg(fc_b + 1);
            if (t < L) {
                const float* hr = &s_h[cp & 1][lane][0];
#pragma unroll
                for (int j = 0; j < Hq; j++) {
                    float hv = hr[j];
                    o0 = fmaf(__ldg(fc_w + j), hv, o0);
                    o1 = fmaf(__ldg(fc_w + Hq + j), hv, o1);
                }
            }
            float2 v = make_float2(o0, o1);
            *reinterpret_cast<float2*>(out + ((size_t)b * Tq + t) * Oq) = v;
        }
    } else {
        // ================= producers (warps 2,3), one chunk ahead =================
        float wiA[Iq], wiB[Iq], wiC[Iq];
#pragma unroll
        for (int i = 0; i < Iq; i++) {
            wiA[i] = 0.5f * w_ih[lane * Iq + i];          // pre-scaled for tanh-form
            wiB[i] = 0.5f * w_ih[(Hq + lane) * Iq + i];
            wiC[i] = w_ih[(2 * Hq + lane) * Iq + i];      // pn: unscaled
        }
        const float biA = 0.5f * (b_ih[lane] + b_hh[lane]);
        const float biB = 0.5f * (b_ih[Hq + lane] + b_hh[Hq + lane]);
        const float biC = b_ih[2 * Hq + lane];
        const int s0 = (warp == 3) ? (CH / 2) : 0;

        // prologue: chunk 0
        {
            const float* xp = x + ((size_t)b * Tq + s0) * Iq;
#pragma unroll 1
            for (int s = 0; s < CH / 2; s++) {
                float xv[Iq];
#pragma unroll
                for (int i = 0; i < Iq; i++) xv[i] = xp[i];
                float gr = biA, gz = biB, gn = biC;
#pragma unroll
                for (int i = 0; i < Iq; i++) {
                    gr = fmaf(wiA[i], xv[i], gr);
                    gz = fmaf(wiB[i], xv[i], gz);
                    gn = fmaf(wiC[i], xv[i], gn);
                }
                s_gx[0][s0 + s][lane] = make_float4(gr, gz, gn, 0.0f);
                xp += Iq;
            }
        }
        for (int c = 0; c < NCH; c++) {
            __syncthreads();
            const int cc = c + 1;
            if (cc < NCH) {
                const float* xp = x + ((size_t)b * Tq + cc * CH + s0) * Iq;
#pragma unroll 1
                for (int s = 0; s < CH / 2; s++) {
                    float xv[Iq];
#pragma unroll
                    for (int i = 0; i < Iq; i++) xv[i] = xp[i];
                    float gr = biA, gz = biB, gn = biC;
#pragma unroll
                    for (int i = 0; i < Iq; i++) {
                        gr = fmaf(wiA[i], xv[i], gr);
                        gz = fmaf(wiB[i], xv[i], gz);
                        gn = fmaf(wiC[i], xv[i], gn);
                    }
                    s_gx[cc & 1][s0 + s][lane] = make_float4(gr, gz, gn, 0.0f);
                    xp += Iq;
                }
            }
        }
        __syncthreads();
    }
}

extern "C" void kernel_launch(void* const* d_in, const int* in_sizes, int n_in,
                              void* d_out, int out_size) {
    const float* x       = (const float*)d_in[0];
    const int*   lengths = (const int*)d_in[1];
    const float* w_ih    = (const float*)d_in[2];
    const float* w_hh    = (const float*)d_in[3];
    const float* b_ih    = (const float*)d_in[4];
    const float* b_hh    = (const float*)d_in[5];
    const float* fc_w    = (const float*)d_in[6];
    const float* fc_b    = (const float*)d_in[7];
    float* out = (float*)d_out;

    gru_seq_kernel<<<Bq, 128>>>(x, lengths, w_ih, w_hh, b_ih, b_hh, fc_w, fc_b, out);
}